// round 5
// baseline (speedup 1.0000x reference)
#include <cuda_runtime.h>
#include <math.h>

#define N_ATOMS 20000
#define N_EDGES 640000
#define FDIM    128
#define F3      (3 * FDIM)      // 384
#define N_RADIAL 20
#define CUTOFF  5.0f
#define PI_F    3.14159265358979323846f

typedef unsigned long long u64;

// ---------------- scratch (static device globals; no runtime allocs) -------
__device__ float g_x[(size_t)N_ATOMS * F3];   // node context [N,3F]
__device__ int   g_count[N_ATOMS];
__device__ int   g_off[N_ATOMS + 1];
__device__ int   g_cursor[N_ATOMS];
__device__ int2  g_pj[N_EDGES];               // slot -> (edge id, source j)

// ---------------- f32x2 packed helpers -------------------------------------
__device__ __forceinline__ u64 pack2(float x, float y) {
    u64 r; asm("mov.b64 %0, {%1,%2};" : "=l"(r) : "f"(x), "f"(y)); return r;
}
__device__ __forceinline__ void unpack2(u64 v, float& x, float& y) {
    asm("mov.b64 {%0,%1}, %2;" : "=f"(x), "=f"(y) : "l"(v));
}
__device__ __forceinline__ void fma2(u64& d, u64 a, u64 b) {
    asm("fma.rn.f32x2 %0, %1, %2, %0;" : "+l"(d) : "l"(a), "l"(b));
}

// ---------------------------------------------------------------------------
// Kernel 1: node MLP, f32x2 packed.  32 rows / 256 threads.
// q and h staged TRANSPOSED in shared ([k][row]) so row-pairs are contiguous:
// broadcast LDS.64 feeds fma.rn.f32x2 -> half the FMA issue count.
// ---------------------------------------------------------------------------
#define MROWS 32
#define MSTR  (MROWS + 2)   // 34: even (8B-aligned pairs), only 2-way STS conflict

__global__ __launch_bounds__(256)
void mlp_kernel(const float* __restrict__ q,
                const float* __restrict__ W1, const float* __restrict__ b1,
                const float* __restrict__ W2, const float* __restrict__ b2,
                float* __restrict__ x)
{
    __shared__ float qs[FDIM][MSTR];   // 17408 B
    __shared__ float hs[FDIM][MSTR];   // 17408 B

    const int f    = threadIdx.x & 127;
    const int half = threadIdx.x >> 7;      // 0/1
    const int r0   = half * 16;              // local row base (16 rows/half)
    const int row0 = blockIdx.x * MROWS;

    // load q transposed: coalesced LDG, scattered (2-way) STS
    for (int idx = threadIdx.x; idx < MROWS * FDIM; idx += 256) {
        const int row = idx >> 7, k = idx & 127;
        qs[k][row] = q[(size_t)(row0 + row) * FDIM + k];
    }
    __syncthreads();

    // stage 1: h = silu(q @ W1 + b1), row-pairs packed
    {
        u64 acc[8];
        const float bb = b1[f];
        const u64 binit = pack2(bb, bb);
        #pragma unroll
        for (int m = 0; m < 8; m++) acc[m] = binit;

        for (int k = 0; k < FDIM; k++) {
            const float w = W1[k * FDIM + f];
            const u64 ww = pack2(w, w);
            #pragma unroll
            for (int m = 0; m < 8; m++) {
                const u64 qq = *(const u64*)&qs[k][r0 + 2 * m];
                fma2(acc[m], ww, qq);
            }
        }
        #pragma unroll
        for (int m = 0; m < 8; m++) {
            float v0, v1; unpack2(acc[m], v0, v1);
            const float h0 = v0 / (1.0f + __expf(-v0));
            const float h1 = v1 / (1.0f + __expf(-v1));
            *(float2*)&hs[f][r0 + 2 * m] = make_float2(h0, h1);
        }
    }
    __syncthreads();

    // stage 2: x = h @ W2 + b2 (3 output slabs), row-pairs packed
    {
        u64 a0[8], a1[8], a2[8];
        const float c0 = b2[f], c1 = b2[FDIM + f], c2 = b2[2 * FDIM + f];
        const u64 i0 = pack2(c0, c0), i1 = pack2(c1, c1), i2 = pack2(c2, c2);
        #pragma unroll
        for (int m = 0; m < 8; m++) { a0[m] = i0; a1[m] = i1; a2[m] = i2; }

        for (int k = 0; k < FDIM; k++) {
            const u64 w0 = pack2(W2[k * F3 + f],            W2[k * F3 + f]);
            const u64 w1 = pack2(W2[k * F3 + FDIM + f],     W2[k * F3 + FDIM + f]);
            const u64 w2 = pack2(W2[k * F3 + 2 * FDIM + f], W2[k * F3 + 2 * FDIM + f]);
            #pragma unroll
            for (int m = 0; m < 8; m++) {
                const u64 hh = *(const u64*)&hs[k][r0 + 2 * m];
                fma2(a0[m], w0, hh);
                fma2(a1[m], w1, hh);
                fma2(a2[m], w2, hh);
            }
        }
        #pragma unroll
        for (int m = 0; m < 8; m++) {
            const size_t ra = (size_t)(row0 + r0 + 2 * m) * F3;
            const size_t rb = ra + F3;
            float v0, v1;
            unpack2(a0[m], v0, v1); x[ra + f]            = v0; x[rb + f]            = v1;
            unpack2(a1[m], v0, v1); x[ra + FDIM + f]     = v0; x[rb + FDIM + f]     = v1;
            unpack2(a2[m], v0, v1); x[ra + 2 * FDIM + f] = v0; x[rb + 2 * FDIM + f] = v1;
        }
    }
}

// ---------------------------------------------------------------------------
// CSR construction: memset -> histogram -> scan -> scatter
// ---------------------------------------------------------------------------
__global__ void hist_kernel(const int* __restrict__ edge_index)
{
    int e = blockIdx.x * blockDim.x + threadIdx.x;
    if (e < N_EDGES) atomicAdd(&g_count[edge_index[e]], 1);
}

__global__ __launch_bounds__(1024)
void scan_kernel()
{
    __shared__ int warp_sums[32];
    __shared__ int chunk_carry;
    const int tid  = threadIdx.x;
    const int lane = tid & 31;
    const int wid  = tid >> 5;
    if (tid == 0) chunk_carry = 0;
    __syncthreads();

    const int nchunks = (N_ATOMS + 1023) / 1024;
    for (int c = 0; c < nchunks; c++) {
        int idx = c * 1024 + tid;
        int v = (idx < N_ATOMS) ? g_count[idx] : 0;
        int s = v;
        #pragma unroll
        for (int o = 1; o < 32; o <<= 1) {
            int t = __shfl_up_sync(0xffffffffu, s, o);
            if (lane >= o) s += t;
        }
        if (lane == 31) warp_sums[wid] = s;
        __syncthreads();
        if (wid == 0) {
            int ws = warp_sums[lane];
            #pragma unroll
            for (int o = 1; o < 32; o <<= 1) {
                int t = __shfl_up_sync(0xffffffffu, ws, o);
                if (lane >= o) ws += t;
            }
            warp_sums[lane] = ws;
        }
        __syncthreads();
        int warp_off = (wid > 0) ? warp_sums[wid - 1] : 0;
        int excl = chunk_carry + warp_off + s - v;
        if (idx < N_ATOMS) { g_off[idx] = excl; g_cursor[idx] = excl; }
        __syncthreads();
        if (tid == 1023) chunk_carry += warp_off + s;
    }
    __syncthreads();
    if (tid == 0) g_off[N_ATOMS] = chunk_carry;
}

__global__ void scatter_kernel(const int* __restrict__ edge_index)
{
    int e = blockIdx.x * blockDim.x + threadIdx.x;
    if (e < N_EDGES) {
        int pos = atomicAdd(&g_cursor[edge_index[e]], 1);
        g_pj[pos] = make_int2(e, edge_index[N_EDGES + e]);
    }
}

// ---------------------------------------------------------------------------
// Kernel 2 (fused): per-node accumulation.
// Block = one node, 128 threads.  Stages 64-edge chunks: one thread/edge
// computes geometry + duplicated basis PAIRS laid out for LDS.128.
// Inner loop: 10 LDS.128 + split-chain f32x2 matvec + 6 hoisted L2 gathers.
// No atomics, final outputs written directly.
// ---------------------------------------------------------------------------
#define CHUNK 64
#define RECW  52    // 4 hdr + 40 dup pairs + pad; mult of 4 (16B-aligned rows)

__global__ __launch_bounds__(128)
void node_kernel(const float* __restrict__ q,
                 const float* __restrict__ mu,
                 const float* __restrict__ ew,
                 const float* __restrict__ Wf,
                 const float* __restrict__ bf,
                 float* __restrict__ qout,
                 float* __restrict__ muout)
{
    __shared__ float srec[CHUNK][RECW];   // 13312 B
    __shared__ int   sj[CHUNK];

    const int i = blockIdx.x;
    const int c = threadIdx.x;

    // Wf slices in registers (identical across blocks -> L1-hot broadcast)
    u64   wqr[N_RADIAL];
    float wm[N_RADIAL];
    #pragma unroll
    for (int r = 0; r < N_RADIAL; r++) {
        wqr[r] = pack2(Wf[r * F3 + c], Wf[r * F3 + FDIM + c]);
        wm[r]  = Wf[r * F3 + 2 * FDIM + c];
    }
    const float bq = bf[c], bR = bf[FDIM + c], bm = bf[2 * FDIM + c];

    const int beg = g_off[i];
    const int end = g_off[i + 1];

    float aq = 0.0f, a0 = 0.0f, a1 = 0.0f, a2 = 0.0f;

    for (int base = beg; base < end; base += CHUNK) {
        const int m = min(CHUNK, end - base);

        __syncthreads();   // previous chunk fully consumed before overwrite
        if (c < m) {
            const int2 pj = g_pj[base + c];
            const int  e  = pj.x;
            sj[c] = pj.y;

            const float ex = ew[3 * e + 0];
            const float ey = ew[3 * e + 1];
            const float ez = ew[3 * e + 2];
            const float dd = fmaf(ex, ex, fmaf(ey, ey, ez * ez));
            const float rd = rsqrtf(dd);
            const float d  = dd * rd;

            float s1, c1;
            __sincosf(d * (PI_F / CUTOFF), &s1, &c1);
            float env = 0.5f * (c1 + 1.0f);
            env = (d < CUTOFF) ? env : 0.0f;

            float* row = srec[c];
            *(float4*)&row[0] = make_float4(ex * rd, ey * rd, ez * rd, env);

            const float re    = rd * env;
            const float two_c = 2.0f * c1;
            float sm1 = 0.0f, sn = s1;
            #pragma unroll
            for (int p = 0; p < N_RADIAL / 2; p++) {
                const float b0 = sn * re;
                const float n1 = two_c * sn - sm1;             // sin((2p+2)x)
                const float b1 = n1 * re;
                const float n2 = two_c * n1 - sn;              // sin((2p+3)x)
                sm1 = n1; sn = n2;
                *(float4*)&row[4 + 4 * p] = make_float4(b0, b0, b1, b1);
            }
        }
        __syncthreads();

        #pragma unroll 2
        for (int t = 0; t < m; t++) {
            const int j = sj[t];
            // gathers issued first: matvec below covers their L2 latency
            const float* xr = g_x + (size_t)j * F3;
            const float* mr = mu  + (size_t)j * F3;
            const float x0 = xr[c], x1 = xr[FDIM + c], x2 = xr[2 * FDIM + c];
            const float m0 = mr[c], m1 = mr[FDIM + c], m2 = mr[2 * FDIM + c];

            const float4 hdr = *(const float4*)&srec[t][0];
            const float env  = hdr.w;

            // split-chain packed matvec (depth 10 per chain)
            u64   fA = pack2(bq * env, bR * env);
            u64   fB = pack2(0.0f, 0.0f);
            float fmA = bm * env, fmB = 0.0f;
            #pragma unroll
            for (int p = 0; p < N_RADIAL / 2; p++) {
                const float4 bb = *(const float4*)&srec[t][4 + 4 * p];
                fma2(fA, pack2(bb.x, bb.y), wqr[2 * p]);
                fma2(fB, pack2(bb.z, bb.w), wqr[2 * p + 1]);
                fmA = fmaf(bb.x, wm[2 * p],     fmA);
                fmB = fmaf(bb.z, wm[2 * p + 1], fmB);
            }
            float fqA, fRA, fqB, fRB;
            unpack2(fA, fqA, fRA);
            unpack2(fB, fqB, fRB);
            const float fq = fqA + fqB;
            const float fR = fRA + fRB;
            const float fm = fmA + fmB;

            aq = fmaf(fq, x0, aq);
            const float dR = fR * x1;
            const float dm = fm * x2;
            a0 = fmaf(dR, hdr.x, fmaf(dm, m0, a0));
            a1 = fmaf(dR, hdr.y, fmaf(dm, m1, a1));
            a2 = fmaf(dR, hdr.z, fmaf(dm, m2, a2));
        }
    }

    qout[(size_t)i * FDIM + c] = q[(size_t)i * FDIM + c] + aq;
    float* mo = muout + (size_t)i * F3;
    const float* mi = mu + (size_t)i * F3;
    mo[c]            = mi[c]            + a0;
    mo[FDIM + c]     = mi[FDIM + c]     + a1;
    mo[2 * FDIM + c] = mi[2 * FDIM + c] + a2;
}

// ---------------------------------------------------------------------------
extern "C" void kernel_launch(void* const* d_in, const int* in_sizes, int n_in,
                              void* d_out, int out_size)
{
    const float* q   = (const float*)d_in[0];
    const float* mu  = (const float*)d_in[1];
    const int*   ei  = (const int*)  d_in[2];
    const float* ew  = (const float*)d_in[3];
    const float* W1  = (const float*)d_in[4];
    const float* b1  = (const float*)d_in[5];
    const float* W2  = (const float*)d_in[6];
    const float* b2  = (const float*)d_in[7];
    const float* Wf  = (const float*)d_in[8];
    const float* bf  = (const float*)d_in[9];

    float* out   = (float*)d_out;
    float* qout  = out;                                   // [N, F]
    float* muout = out + (size_t)N_ATOMS * FDIM;          // [N, 3, F]

    float* fx; cudaGetSymbolAddress((void**)&fx, g_x);
    int*   fc; cudaGetSymbolAddress((void**)&fc, g_count);

    // CSR build (destination-grouped edge order)
    cudaMemsetAsync(fc, 0, N_ATOMS * sizeof(int), 0);
    hist_kernel<<<N_EDGES / 256, 256>>>(ei);
    scan_kernel<<<1, 1024>>>();
    scatter_kernel<<<N_EDGES / 256, 256>>>(ei);

    // node MLP -> g_x (f32x2 packed)
    mlp_kernel<<<N_ATOMS / MROWS, 256>>>(q, W1, b1, W2, b2, fx);

    // fused geometry + filter + pull accumulation, writes final outputs
    node_kernel<<<N_ATOMS, 128>>>(q, mu, ew, Wf, bf, qout, muout);
}

// round 6
// speedup vs baseline: 1.2055x; 1.2055x over previous
#include <cuda_runtime.h>
#include <math.h>

#define N_ATOMS 20000
#define N_EDGES 640000
#define FDIM    128
#define F3      (3 * FDIM)      // 384
#define N_RADIAL 20
#define CUTOFF  5.0f
#define PI_F    3.14159265358979323846f

typedef unsigned long long u64;

// ---------------- scratch (static device globals; no runtime allocs) -------
__device__ float g_x[(size_t)N_ATOMS * F3];   // node context [N,3F]
__device__ int   g_count[N_ATOMS];
__device__ int   g_off[N_ATOMS + 1];
__device__ int   g_cursor[N_ATOMS];
__device__ int2  g_pj[N_EDGES];               // slot -> (edge id, source j)

// ---------------- f32x2 packed helpers -------------------------------------
__device__ __forceinline__ u64 pack2(float x, float y) {
    u64 r; asm("mov.b64 %0, {%1,%2};" : "=l"(r) : "f"(x), "f"(y)); return r;
}
__device__ __forceinline__ void unpack2(u64 v, float& x, float& y) {
    asm("mov.b64 {%0,%1}, %2;" : "=f"(x), "=f"(y) : "l"(v));
}
__device__ __forceinline__ void fma2(u64& d, u64 a, u64 b) {
    asm("fma.rn.f32x2 %0, %1, %2, %0;" : "+l"(d) : "l"(a), "l"(b));
}

// ---------------------------------------------------------------------------
// Kernel 1: node MLP, scalar FFMA (independent chains), k unrolled by 4 with
// LDS.128 broadcast reads.  32 rows / 256 threads (2 halves x 16 rows).
// ---------------------------------------------------------------------------
#define MROWS 32

__global__ __launch_bounds__(256)
void mlp_kernel(const float* __restrict__ q,
                const float* __restrict__ W1, const float* __restrict__ b1,
                const float* __restrict__ W2, const float* __restrict__ b2,
                float* __restrict__ x)
{
    __shared__ float qs[MROWS][FDIM];   // 16 KB, k fastest (float4-able)
    __shared__ float hs[MROWS][FDIM];   // 16 KB

    const int f    = threadIdx.x & 127;
    const int half = threadIdx.x >> 7;       // 0/1
    const int r0   = half * 16;               // local row base
    const int row0 = blockIdx.x * MROWS;

    for (int idx = threadIdx.x; idx < MROWS * FDIM; idx += 256)
        qs[idx >> 7][idx & 127] = q[(size_t)row0 * FDIM + idx];
    __syncthreads();

    // stage 1: h = silu(q @ W1 + b1)
    {
        float acc[16];
        const float bb = b1[f];
        #pragma unroll
        for (int r = 0; r < 16; r++) acc[r] = bb;

        for (int k = 0; k < FDIM; k += 4) {
            const float w0 = W1[(k + 0) * FDIM + f];
            const float w1 = W1[(k + 1) * FDIM + f];
            const float w2 = W1[(k + 2) * FDIM + f];
            const float w3 = W1[(k + 3) * FDIM + f];
            #pragma unroll
            for (int r = 0; r < 16; r++) {
                const float4 qv = *(const float4*)&qs[r0 + r][k];  // LDS.128 bcast
                acc[r] = fmaf(qv.x, w0, acc[r]);
                acc[r] = fmaf(qv.y, w1, acc[r]);
                acc[r] = fmaf(qv.z, w2, acc[r]);
                acc[r] = fmaf(qv.w, w3, acc[r]);
            }
        }
        #pragma unroll
        for (int r = 0; r < 16; r++) {
            const float v = acc[r];
            hs[r0 + r][f] = v / (1.0f + __expf(-v));
        }
    }
    __syncthreads();

    // stage 2: x = h @ W2 + b2
    {
        float a0[16], a1[16], a2[16];
        const float c0 = b2[f], c1 = b2[FDIM + f], c2 = b2[2 * FDIM + f];
        #pragma unroll
        for (int r = 0; r < 16; r++) { a0[r] = c0; a1[r] = c1; a2[r] = c2; }

        for (int k = 0; k < FDIM; k += 4) {
            float wa[4], wb[4], wc[4];
            #pragma unroll
            for (int u = 0; u < 4; u++) {
                wa[u] = W2[(k + u) * F3 + f];
                wb[u] = W2[(k + u) * F3 + FDIM + f];
                wc[u] = W2[(k + u) * F3 + 2 * FDIM + f];
            }
            #pragma unroll
            for (int r = 0; r < 16; r++) {
                const float4 hv = *(const float4*)&hs[r0 + r][k];  // LDS.128 bcast
                a0[r] = fmaf(hv.x, wa[0], a0[r]);
                a0[r] = fmaf(hv.y, wa[1], a0[r]);
                a0[r] = fmaf(hv.z, wa[2], a0[r]);
                a0[r] = fmaf(hv.w, wa[3], a0[r]);
                a1[r] = fmaf(hv.x, wb[0], a1[r]);
                a1[r] = fmaf(hv.y, wb[1], a1[r]);
                a1[r] = fmaf(hv.z, wb[2], a1[r]);
                a1[r] = fmaf(hv.w, wb[3], a1[r]);
                a2[r] = fmaf(hv.x, wc[0], a2[r]);
                a2[r] = fmaf(hv.y, wc[1], a2[r]);
                a2[r] = fmaf(hv.z, wc[2], a2[r]);
                a2[r] = fmaf(hv.w, wc[3], a2[r]);
            }
        }
        #pragma unroll
        for (int r = 0; r < 16; r++) {
            const size_t base = (size_t)(row0 + r0 + r) * F3;
            x[base + f]            = a0[r];
            x[base + FDIM + f]     = a1[r];
            x[base + 2 * FDIM + f] = a2[r];
        }
    }
}

// ---------------------------------------------------------------------------
// CSR construction: memset -> histogram -> scan -> scatter
// ---------------------------------------------------------------------------
__global__ void hist_kernel(const int* __restrict__ edge_index)
{
    int e = blockIdx.x * blockDim.x + threadIdx.x;
    if (e < N_EDGES) atomicAdd(&g_count[edge_index[e]], 1);
}

__global__ __launch_bounds__(1024)
void scan_kernel()
{
    __shared__ int warp_sums[32];
    __shared__ int chunk_carry;
    const int tid  = threadIdx.x;
    const int lane = tid & 31;
    const int wid  = tid >> 5;
    if (tid == 0) chunk_carry = 0;
    __syncthreads();

    const int nchunks = (N_ATOMS + 1023) / 1024;
    for (int c = 0; c < nchunks; c++) {
        int idx = c * 1024 + tid;
        int v = (idx < N_ATOMS) ? g_count[idx] : 0;
        int s = v;
        #pragma unroll
        for (int o = 1; o < 32; o <<= 1) {
            int t = __shfl_up_sync(0xffffffffu, s, o);
            if (lane >= o) s += t;
        }
        if (lane == 31) warp_sums[wid] = s;
        __syncthreads();
        if (wid == 0) {
            int ws = warp_sums[lane];
            #pragma unroll
            for (int o = 1; o < 32; o <<= 1) {
                int t = __shfl_up_sync(0xffffffffu, ws, o);
                if (lane >= o) ws += t;
            }
            warp_sums[lane] = ws;
        }
        __syncthreads();
        int warp_off = (wid > 0) ? warp_sums[wid - 1] : 0;
        int excl = chunk_carry + warp_off + s - v;
        if (idx < N_ATOMS) { g_off[idx] = excl; g_cursor[idx] = excl; }
        __syncthreads();
        if (tid == 1023) chunk_carry += warp_off + s;
    }
    __syncthreads();
    if (tid == 0) g_off[N_ATOMS] = chunk_carry;
}

__global__ void scatter_kernel(const int* __restrict__ edge_index)
{
    int e = blockIdx.x * blockDim.x + threadIdx.x;
    if (e < N_EDGES) {
        int pos = atomicAdd(&g_cursor[edge_index[e]], 1);
        g_pj[pos] = make_int2(e, edge_index[N_EDGES + e]);
    }
}

// ---------------------------------------------------------------------------
// Kernel 2 (fused): per-node accumulation (R4 configuration).
// Block = one node, 128 threads.  Stages 64-edge chunks in shared; inner loop
// reads duplicated basis pairs via LDS.64 broadcast into fma.rn.f32x2.
// No atomics; final outputs written directly.
// ---------------------------------------------------------------------------
#define CHUNK 64
#define RECW  46    // 4 scalars + 20 duplicated pairs (44), padded to even 46

__global__ __launch_bounds__(128)
void node_kernel(const float* __restrict__ q,
                 const float* __restrict__ mu,
                 const float* __restrict__ ew,
                 const float* __restrict__ Wf,
                 const float* __restrict__ bf,
                 float* __restrict__ qout,
                 float* __restrict__ muout)
{
    __shared__ float srec[CHUNK][RECW];   // 11776 B
    __shared__ int   sj[CHUNK];

    const int i = blockIdx.x;
    const int c = threadIdx.x;

    // Wf slices in registers (identical across blocks -> L1-hot broadcast)
    u64   wqr[N_RADIAL];
    float wm[N_RADIAL];
    #pragma unroll
    for (int r = 0; r < N_RADIAL; r++) {
        wqr[r] = pack2(Wf[r * F3 + c], Wf[r * F3 + FDIM + c]);
        wm[r]  = Wf[r * F3 + 2 * FDIM + c];
    }
    const float bq = bf[c], bR = bf[FDIM + c], bm = bf[2 * FDIM + c];

    const int beg = g_off[i];
    const int end = g_off[i + 1];

    float aq = 0.0f, a0 = 0.0f, a1 = 0.0f, a2 = 0.0f;

    for (int base = beg; base < end; base += CHUNK) {
        const int m = min(CHUNK, end - base);

        __syncthreads();   // previous chunk fully consumed before overwrite
        if (c < m) {
            const int2 pj = g_pj[base + c];
            const int  e  = pj.x;
            sj[c] = pj.y;

            const float ex = ew[3 * e + 0];
            const float ey = ew[3 * e + 1];
            const float ez = ew[3 * e + 2];
            const float dd = fmaf(ex, ex, fmaf(ey, ey, ez * ez));
            const float rd = rsqrtf(dd);
            const float d  = dd * rd;

            float s1, c1;
            __sincosf(d * (PI_F / CUTOFF), &s1, &c1);
            float env = 0.5f * (c1 + 1.0f);
            env = (d < CUTOFF) ? env : 0.0f;

            float* row = srec[c];
            row[0] = ex * rd;
            row[1] = ey * rd;
            row[2] = ez * rd;
            row[3] = env;

            const float re    = rd * env;
            const float two_c = 2.0f * c1;
            float sm1 = 0.0f, sn = s1;
            #pragma unroll
            for (int n = 0; n < N_RADIAL; n++) {
                const float b = sn * re;
                row[4 + 2 * n] = b;    // duplicated pair for LDS.64 -> fma2
                row[5 + 2 * n] = b;
                const float nx = two_c * sn - sm1;
                sm1 = sn; sn = nx;
            }
        }
        __syncthreads();

        #pragma unroll 2
        for (int t = 0; t < m; t++) {
            const int j = sj[t];
            const float d0  = srec[t][0];
            const float d1  = srec[t][1];
            const float d2  = srec[t][2];
            const float env = srec[t][3];

            u64   fqr = pack2(bq * env, bR * env);
            float fm  = bm * env;
            #pragma unroll
            for (int r = 0; r < N_RADIAL; r++) {
                const float2 b2v = *(const float2*)&srec[t][4 + 2 * r];  // LDS.64 bcast
                fma2(fqr, pack2(b2v.x, b2v.y), wqr[r]);
                fm = fmaf(b2v.x, wm[r], fm);
            }
            float fq, fR; unpack2(fqr, fq, fR);

            const float* xr = g_x + (size_t)j * F3;
            const float dq = fq * xr[c];
            const float dR = fR * xr[FDIM + c];
            const float dm = fm * xr[2 * FDIM + c];

            const float* mr = mu + (size_t)j * F3;
            aq += dq;
            a0 = fmaf(dR, d0, fmaf(dm, mr[c],            a0));
            a1 = fmaf(dR, d1, fmaf(dm, mr[FDIM + c],     a1));
            a2 = fmaf(dR, d2, fmaf(dm, mr[2 * FDIM + c], a2));
        }
    }

    qout[(size_t)i * FDIM + c] = q[(size_t)i * FDIM + c] + aq;
    float* mo = muout + (size_t)i * F3;
    const float* mi = mu + (size_t)i * F3;
    mo[c]            = mi[c]            + a0;
    mo[FDIM + c]     = mi[FDIM + c]     + a1;
    mo[2 * FDIM + c] = mi[2 * FDIM + c] + a2;
}

// ---------------------------------------------------------------------------
extern "C" void kernel_launch(void* const* d_in, const int* in_sizes, int n_in,
                              void* d_out, int out_size)
{
    const float* q   = (const float*)d_in[0];
    const float* mu  = (const float*)d_in[1];
    const int*   ei  = (const int*)  d_in[2];
    const float* ew  = (const float*)d_in[3];
    const float* W1  = (const float*)d_in[4];
    const float* b1  = (const float*)d_in[5];
    const float* W2  = (const float*)d_in[6];
    const float* b2  = (const float*)d_in[7];
    const float* Wf  = (const float*)d_in[8];
    const float* bf  = (const float*)d_in[9];

    float* out   = (float*)d_out;
    float* qout  = out;                                   // [N, F]
    float* muout = out + (size_t)N_ATOMS * FDIM;          // [N, 3, F]

    float* fx; cudaGetSymbolAddress((void**)&fx, g_x);
    int*   fc; cudaGetSymbolAddress((void**)&fc, g_count);

    // CSR build (destination-grouped edge order)
    cudaMemsetAsync(fc, 0, N_ATOMS * sizeof(int), 0);
    hist_kernel<<<N_EDGES / 256, 256>>>(ei);
    scan_kernel<<<1, 1024>>>();
    scatter_kernel<<<N_EDGES / 256, 256>>>(ei);

    // node MLP -> g_x (scalar FFMA, LDS.128 k-unroll)
    mlp_kernel<<<N_ATOMS / MROWS, 256>>>(q, W1, b1, W2, b2, fx);

    // fused geometry + filter + pull accumulation, writes final outputs
    node_kernel<<<N_ATOMS, 128>>>(q, mu, ew, Wf, bf, qout, muout);
}